// round 4
// baseline (speedup 1.0000x reference)
#include <cuda_runtime.h>
#include <cstdint>

#define NVOX 400000
#define NPTS 800000

// ---------------- scratch (device globals; zero-initialized at load) -------
__device__ float g_red [(size_t)NVOX * 64];        // 102.4 MB
__device__ float g_s32 [(size_t)4 * NVOX * 32];    // 204.8 MB (ssum @ W_att, 32-wide)
__device__ float g_cnt [(size_t)4 * NVOX];         // 6.4 MB
__device__ float g_att [(size_t)4 * NVOX * 32];    // 204.8 MB
__device__ float g_proj[(size_t)NVOX * 64];        // 102.4 MB
__device__ int   g_vout[(size_t)NVOX];             // voxel -> out-row+1 (0 = absent)
__device__ float g_Wc  [32 * 64];                  // W_out @ W_lin1[64:128]

__device__ __forceinline__ float sigm(float x) { return 1.f / (1.f + __expf(-x)); }

__device__ __forceinline__ void amaxf(float* a, float v) {
    if (v >= 0.f) atomicMax((int*)a, __float_as_int(v));
    else          atomicMin((unsigned int*)a, __float_as_uint(v));
}

__device__ __forceinline__ void red4(float* p, float a, float b, float c, float d) {
    asm volatile("red.global.add.v4.f32 [%0], {%1,%2,%3,%4};"
                 :: "l"(p), "f"(a), "f"(b), "f"(c), "f"(d) : "memory");
}

// ---- packed fp32x2 helpers (Blackwell FFMA2 — only reachable via PTX) -----
__device__ __forceinline__ uint64_t pk2(float lo, float hi) {
    uint64_t r; asm("mov.b64 %0, {%1,%2};" : "=l"(r) : "f"(lo), "f"(hi)); return r;
}
__device__ __forceinline__ uint64_t bc2(float v) { return pk2(v, v); }
__device__ __forceinline__ void fma2(uint64_t& d, uint64_t a, uint64_t b) {
    asm("fma.rn.f32x2 %0, %1, %2, %0;" : "+l"(d) : "l"(a), "l"(b));
}
__device__ __forceinline__ float2 up2(uint64_t v) {
    float2 f; asm("mov.b64 {%0,%1}, %2;" : "=f"(f.x), "=f"(f.y) : "l"(v)); return f;
}

// ---------------- init kernels ---------------------------------------------
__global__ void k_fill_out(float* __restrict__ out, int n) {
    int i = blockIdx.x * blockDim.x + threadIdx.x;
    if (i < n) ((unsigned int*)out)[i] = 0xFF800000u;   // -inf
}

// Wc[k][c] = sum_t W_out[k][t] * W_lin1[64+t][c]
__global__ void k_wc(const float* __restrict__ Wout, const float* __restrict__ W1) {
    int idx = blockIdx.x * blockDim.x + threadIdx.x;   // 2048 = 32*64
    if (idx >= 32 * 64) return;
    int k = idx >> 6, c = idx & 63;
    float s = 0.f;
    for (int t = 0; t < 64; t++) s += Wout[k * 64 + t] * W1[(64 + t) * 64 + c];
    g_Wc[idx] = s;
}

// ---------------- K1: red = relu(x@Wred+b); scatter red@W_att[j] (32-wide) -
__global__ __launch_bounds__(128, 4) void k_red(
    const float* __restrict__ x, const float* __restrict__ W,
    const float* __restrict__ b, const float* __restrict__ Watt,
    const int* __restrict__ i0, const int* __restrict__ i1,
    const int* __restrict__ i2, const int* __restrict__ i3)
{
    __shared__ float sW[64 * 64];      // 16 KB  W_red
    __shared__ float sA[4 * 64 * 32];  // 32 KB  W_att (all 4 scales)
    int tid = threadIdx.x;
    for (int i = tid; i < 64 * 16; i += 128) ((float4*)sW)[i] = ((const float4*)W)[i];
    for (int i = tid; i < 4 * 64 * 8; i += 128) ((float4*)sA)[i] = ((const float4*)Watt)[i];
    __syncthreads();

    int v = blockIdx.x * 128 + tid;
    if (v >= NVOX) return;
    const float4* xr = (const float4*)(x + (size_t)v * 64);
    const uint64_t* W2 = (const uint64_t*)sW;

    uint64_t acc[32];
#pragma unroll
    for (int c = 0; c < 32; c++) acc[c] = 0ull;

#pragma unroll
    for (int kq = 0; kq < 16; kq++) {
        float4 x4 = __ldg(xr + kq);
        float xv[4] = {x4.x, x4.y, x4.z, x4.w};
#pragma unroll
        for (int kk = 0; kk < 4; kk++) {
            uint64_t xb = bc2(xv[kk]);
            int k = kq * 4 + kk;
#pragma unroll
            for (int c2 = 0; c2 < 32; c2++) fma2(acc[c2], xb, W2[k * 32 + c2]);
        }
    }
    float red[64];
#pragma unroll
    for (int c2 = 0; c2 < 32; c2++) {
        float2 f = up2(acc[c2]);
        red[2 * c2 + 0] = fmaxf(f.x + __ldg(b + 2 * c2 + 0), 0.f);
        red[2 * c2 + 1] = fmaxf(f.y + __ldg(b + 2 * c2 + 1), 0.f);
    }

    float4* rr = (float4*)(g_red + (size_t)v * 64);
#pragma unroll
    for (int q = 0; q < 16; q++)
        rr[q] = make_float4(red[4 * q], red[4 * q + 1], red[4 * q + 2], red[4 * q + 3]);

    const int* invs[4] = {i0, i1, i2, i3};
#pragma unroll
    for (int j = 0; j < 4; j++) {
        const uint64_t* A2 = (const uint64_t*)(sA + j * 2048);
        uint64_t t2[16];
#pragma unroll
        for (int c2 = 0; c2 < 16; c2++) t2[c2] = 0ull;
#pragma unroll
        for (int k = 0; k < 64; k++) {
            uint64_t xb = bc2(red[k]);
#pragma unroll
            for (int c2 = 0; c2 < 16; c2++) fma2(t2[c2], xb, A2[k * 16 + c2]);
        }
        int s = __ldg(invs[j] + v);
        float* dst = g_s32 + ((size_t)j * NVOX + s) * 32;
#pragma unroll
        for (int q = 0; q < 8; q++) {
            float2 a = up2(t2[2 * q]), bb = up2(t2[2 * q + 1]);
            red4(dst + q * 4, a.x, a.y, bb.x, bb.y);
        }
        atomicAdd(g_cnt + (size_t)j * NVOX + s, 1.0f);
    }
}

// ---------------- K2: att = relu(s32/cnt + b); self-clean (8 thr/row) ------
__global__ __launch_bounds__(256) void k_scale(const float* __restrict__ batt)
{
    long long t = (long long)blockIdx.x * 256 + threadIdx.x;   // 4*NVOX*8 threads
    long long row = t >> 3;
    int q = (int)(t & 7);
    bool live = false;
    float c = 0.f;
    int j = 0;
    if (row < (long long)4 * NVOX) {
        j = (int)(row / NVOX);
        c = g_cnt[row];
        live = (c != 0.f);
    }
    if (live) {
        float invc = 1.f / c;
        float4* sp = (float4*)(g_s32 + row * 32) + q;
        float4* op = (float4*)(g_att + row * 32) + q;
        float4 v = *sp;
        float4 o;
        o.x = fmaxf(v.x * invc + __ldg(batt + j * 32 + 4 * q + 0), 0.f);
        o.y = fmaxf(v.y * invc + __ldg(batt + j * 32 + 4 * q + 1), 0.f);
        o.z = fmaxf(v.z * invc + __ldg(batt + j * 32 + 4 * q + 2), 0.f);
        o.w = fmaxf(v.w * invc + __ldg(batt + j * 32 + 4 * q + 3), 0.f);
        *op = o;
        *sp = make_float4(0.f, 0.f, 0.f, 0.f);      // restore zero for next replay
    }
    __syncwarp();                                    // all 8 readers of cnt done
    if (live && q == 0) g_cnt[row] = 0.f;            // restore zero for next replay
}

// ---------------- K3: fusion + attention + MLP per voxel -> proj -----------
// dynamic smem layout (floats):
//   [0,4096) Wfcs ; [4096,6144) Wc ; [6144,10240) W1a ; [10240,14336) W2
//   [14336,15360) Wfc ; [15360,15488) bfcs ; [15488,15552) b2
#define FUSE_SMEM_FLOATS 15552
__global__ __launch_bounds__(256, 2) void k_fuse(
    const float* __restrict__ Wfc,  const float* __restrict__ Wfcs,
    const float* __restrict__ bfcs, const float* __restrict__ W1,
    const float* __restrict__ W2,   const float* __restrict__ b2,
    const int* __restrict__ i0, const int* __restrict__ i1,
    const int* __restrict__ i2, const int* __restrict__ i3)
{
    extern __shared__ float sm[];
    float* sWfcs = sm;
    float* sWc   = sm + 4096;
    float* sW1a  = sm + 6144;
    float* sW2   = sm + 10240;
    float* sWfc  = sm + 14336;
    float* sbfcs = sm + 15360;
    float* sb2   = sm + 15488;

    int tid = threadIdx.x;
    for (int i = tid; i < 1024; i += 256) ((float4*)sWfcs)[i] = ((const float4*)Wfcs)[i];
    for (int i = tid; i < 512;  i += 256) ((float4*)sWc)[i]   = ((const float4*)g_Wc)[i];
    for (int i = tid; i < 1024; i += 256) ((float4*)sW1a)[i]  = ((const float4*)W1)[i];
    for (int i = tid; i < 1024; i += 256) ((float4*)sW2)[i]   = ((const float4*)W2)[i];
    for (int i = tid; i < 256;  i += 256) ((float4*)sWfc)[i]  = ((const float4*)Wfc)[i];
    if (tid < 128) sbfcs[tid] = bfcs[tid];
    if (tid < 64)  sb2[tid]   = b2[tid];
    __syncthreads();

    int v = blockIdx.x * 256 + tid;
    if (v >= NVOX) return;
    int sg[4] = {__ldg(i0 + v), __ldg(i1 + v), __ldg(i2 + v), __ldg(i3 + v)};

    // feat_S = sum_j s_j
    float fS[32];
#pragma unroll
    for (int i = 0; i < 32; i++) fS[i] = 0.f;
#pragma unroll
    for (int j = 0; j < 4; j++) {
        const float4* sp = (const float4*)(g_att + ((size_t)j * NVOX + sg[j]) * 32);
#pragma unroll
        for (int q = 0; q < 8; q++) {
            float4 s4 = __ldg(sp + q);
            fS[4 * q + 0] += s4.x; fS[4 * q + 1] += s4.y;
            fS[4 * q + 2] += s4.z; fS[4 * q + 3] += s4.w;
        }
    }

    // feat_Z = relu(feat_S @ W_fc)
    const uint64_t* Wfc2 = (const uint64_t*)sWfc;
    uint64_t z2[16];
#pragma unroll
    for (int i = 0; i < 16; i++) z2[i] = 0ull;
#pragma unroll
    for (int k = 0; k < 32; k++) {
        uint64_t xb = bc2(fS[k]);
#pragma unroll
        for (int c2 = 0; c2 < 16; c2++) fma2(z2[c2], xb, Wfc2[k * 16 + c2]);
    }
    float fZ[32];
#pragma unroll
    for (int c2 = 0; c2 < 16; c2++) {
        float2 f = up2(z2[c2]);
        fZ[2 * c2 + 0] = fmaxf(f.x, 0.f);
        fZ[2 * c2 + 1] = fmaxf(f.y, 0.f);
    }

    // m = sum_j s_j * sigmoid(fZ @ W_fcs[j] + b_fcs[j])
    float m[32];
#pragma unroll
    for (int i = 0; i < 32; i++) m[i] = 0.f;
#pragma unroll
    for (int j = 0; j < 4; j++) {
        const uint64_t* Wj2 = (const uint64_t*)(sWfcs + j * 1024);
        uint64_t a2[16];
#pragma unroll
        for (int c2 = 0; c2 < 16; c2++)
            a2[c2] = pk2(sbfcs[j * 32 + 2 * c2], sbfcs[j * 32 + 2 * c2 + 1]);
#pragma unroll
        for (int k = 0; k < 32; k++) {
            uint64_t xb = bc2(fZ[k]);
#pragma unroll
            for (int c2 = 0; c2 < 16; c2++) fma2(a2[c2], xb, Wj2[k * 16 + c2]);
        }
        const float4* sp = (const float4*)(g_att + ((size_t)j * NVOX + sg[j]) * 32);
#pragma unroll
        for (int q = 0; q < 8; q++) {
            float2 a = up2(a2[2 * q]), bb = up2(a2[2 * q + 1]);
            float4 s4 = __ldg(sp + q);
            m[4 * q + 0] += s4.x * sigm(a.x);
            m[4 * q + 1] += s4.y * sigm(a.y);
            m[4 * q + 2] += s4.z * sigm(bb.x);
            m[4 * q + 3] += s4.w * sigm(bb.y);
        }
    }

    // h = relu(m @ Wc + red @ W1a)
    const uint64_t* Wc2  = (const uint64_t*)sWc;
    const uint64_t* W1a2 = (const uint64_t*)sW1a;
    uint64_t h2[32];
#pragma unroll
    for (int i = 0; i < 32; i++) h2[i] = 0ull;
#pragma unroll
    for (int k = 0; k < 32; k++) {
        uint64_t xb = bc2(m[k]);
#pragma unroll
        for (int c2 = 0; c2 < 32; c2++) fma2(h2[c2], xb, Wc2[k * 32 + c2]);
    }
    const float4* rp = (const float4*)(g_red + (size_t)v * 64);
#pragma unroll
    for (int kq = 0; kq < 16; kq++) {
        float4 r4 = __ldg(rp + kq);
        float xv[4] = {r4.x, r4.y, r4.z, r4.w};
#pragma unroll
        for (int kk = 0; kk < 4; kk++) {
            uint64_t xb = bc2(xv[kk]);
            int k = kq * 4 + kk;
#pragma unroll
            for (int c2 = 0; c2 < 32; c2++) fma2(h2[c2], xb, W1a2[k * 32 + c2]);
        }
    }
    float h[64];
#pragma unroll
    for (int c2 = 0; c2 < 32; c2++) {
        float2 f = up2(h2[c2]);
        h[2 * c2 + 0] = fmaxf(f.x, 0.f);
        h[2 * c2 + 1] = fmaxf(f.y, 0.f);
    }

    // proj = h @ W2 + b2  (two 32-col halves to bound register pressure)
    const uint64_t* W22 = (const uint64_t*)sW2;
    float4* pr = (float4*)(g_proj + (size_t)v * 64);
#pragma unroll
    for (int half = 0; half < 2; half++) {
        uint64_t p2[16];
#pragma unroll
        for (int c2 = 0; c2 < 16; c2++)
            p2[c2] = pk2(sb2[half * 32 + 2 * c2], sb2[half * 32 + 2 * c2 + 1]);
#pragma unroll
        for (int k = 0; k < 64; k++) {
            uint64_t xb = bc2(h[k]);
#pragma unroll
            for (int c2 = 0; c2 < 16; c2++) fma2(p2[c2], xb, W22[k * 32 + half * 16 + c2]);
        }
#pragma unroll
        for (int q = 0; q < 8; q++) {
            float2 a = up2(p2[2 * q]), bb = up2(p2[2 * q + 1]);
            pr[half * 8 + q] = make_float4(a.x, a.y, bb.x, bb.y);
        }
    }
}

// ---------------- K4a: point -> voxel out-row map (idempotent) --------------
__global__ __launch_bounds__(256) void k_map(
    const int* __restrict__ invp, const int* __restrict__ invo)
{
    int p = blockIdx.x * 256 + threadIdx.x;
    if (p >= NPTS) return;
    g_vout[__ldg(invp + p)] = __ldg(invo + p) + 1;
}

// ---------------- K4b: per present voxel, segment-max proj into out --------
__global__ __launch_bounds__(256) void k_pmax(float* __restrict__ out)
{
    int t = blockIdx.x * 256 + threadIdx.x;
    int v = t >> 4, q = t & 15;
    if (v >= NVOX) return;
    int o = g_vout[v];
    if (o == 0) return;                   // voxel not referenced by any point
    o--;
    float4 val = __ldg((const float4*)(g_proj + (size_t)v * 64) + q);
    float* ob = out + (size_t)o * 64 + q * 4;
    amaxf(ob + 0, val.x); amaxf(ob + 1, val.y);
    amaxf(ob + 2, val.z); amaxf(ob + 3, val.w);
}

// ---------------- launch ----------------------------------------------------
// Inputs identified by ELEMENT COUNT + first-appearance order (dict order):
//   400000 x4 -> inv0..inv3 ; 800000 x2 -> inv_pts, inv_out ; 25600000 -> x
//   4096 x3 -> W_red, W_fcs, W_lin2 ; 8192 x2 -> W_att, W_lin1
//   64 x2 -> b_red, b_lin2 ; 128 x2 -> b_att, b_fcs ; 1024 -> W_fc ; 2048 -> W_out
extern "C" void kernel_launch(void* const* d_in, const int* in_sizes, int n_in,
                              void* d_out, int out_size)
{
    const float *x = 0, *Wred = 0, *bred = 0, *Watt = 0, *batt = 0;
    const float *Wfcs = 0, *bfcs = 0, *Wfc = 0, *Wout = 0, *W1 = 0, *W2 = 0, *b2 = 0;
    const int *i0 = 0, *i1 = 0, *i2 = 0, *i3 = 0, *invp = 0, *invo = 0;

    int c400k = 0, c800k = 0, c4096 = 0, c8192 = 0, c64 = 0, c128 = 0;
    for (int i = 0; i < n_in; i++) {
        int s = in_sizes[i];
        const void* p = d_in[i];
        switch (s) {
            case 400000:
                if      (c400k == 0) i0 = (const int*)p;
                else if (c400k == 1) i1 = (const int*)p;
                else if (c400k == 2) i2 = (const int*)p;
                else                 i3 = (const int*)p;
                c400k++; break;
            case 800000:
                if (c800k == 0) invp = (const int*)p; else invo = (const int*)p;
                c800k++; break;
            case 25600000: x = (const float*)p; break;
            case 4096:
                if      (c4096 == 0) Wred = (const float*)p;
                else if (c4096 == 1) Wfcs = (const float*)p;
                else                 W2   = (const float*)p;
                c4096++; break;
            case 8192:
                if (c8192 == 0) Watt = (const float*)p; else W1 = (const float*)p;
                c8192++; break;
            case 64:
                if (c64 == 0) bred = (const float*)p; else b2 = (const float*)p;
                c64++; break;
            case 128:
                if (c128 == 0) batt = (const float*)p; else bfcs = (const float*)p;
                c128++; break;
            case 1024: Wfc  = (const float*)p; break;
            case 2048: Wout = (const float*)p; break;
            default: break;   // size-1 scalars ignored
        }
    }

    float* out = (float*)d_out;

    static int smem_set = 0;
    if (!smem_set) {
        cudaFuncSetAttribute(k_fuse, cudaFuncAttributeMaxDynamicSharedMemorySize,
                             FUSE_SMEM_FLOATS * 4);
        smem_set = 1;
    }

    k_fill_out<<<(out_size + 255) / 256, 256>>>(out, out_size);

    k_wc<<<8, 256>>>(Wout, W1);

    k_map<<<(NPTS + 255) / 256, 256>>>(invp, invo);

    k_red<<<(NVOX + 127) / 128, 128>>>(x, Wred, bred, Watt, i0, i1, i2, i3);

    {
        long long tot = (long long)4 * NVOX * 8;
        k_scale<<<(unsigned)((tot + 255) / 256), 256>>>(batt);
    }

    k_fuse<<<(NVOX + 255) / 256, 256, FUSE_SMEM_FLOATS * 4>>>(
        Wfc, Wfcs, bfcs, W1, W2, b2, i0, i1, i2, i3);

    k_pmax<<<((size_t)NVOX * 16 + 255) / 256, 256>>>(out);
}

// round 5
// speedup vs baseline: 1.3269x; 1.3269x over previous
#include <cuda_runtime.h>
#include <cstdint>

#define NVOX 400000
#define NPTS 800000

// ---------------- scratch (device globals; zero-initialized at load) -------
__device__ float g_rW1 [(size_t)NVOX * 64];        // red @ W_lin1[0:64]  102.4 MB
__device__ float g_ssum[(size_t)4 * NVOX * 64];    // segment sums of red 409.6 MB
__device__ float g_cnt [(size_t)4 * NVOX];         // 6.4 MB
__device__ float g_att [(size_t)4 * NVOX * 32];    // 204.8 MB
__device__ float g_proj[(size_t)NVOX * 64];        // 102.4 MB
__device__ int   g_vout[(size_t)NVOX];             // voxel -> out-row+1 (0 = absent)
__device__ float g_Wc  [32 * 64];                  // W_out @ W_lin1[64:128]

__device__ __forceinline__ float sigm(float x) { return 1.f / (1.f + __expf(-x)); }

__device__ __forceinline__ void amaxf(float* a, float v) {
    if (v >= 0.f) atomicMax((int*)a, __float_as_int(v));
    else          atomicMin((unsigned int*)a, __float_as_uint(v));
}

__device__ __forceinline__ void red4(float* p, float a, float b, float c, float d) {
    asm volatile("red.global.add.v4.f32 [%0], {%1,%2,%3,%4};"
                 :: "l"(p), "f"(a), "f"(b), "f"(c), "f"(d) : "memory");
}

// ---------------- init kernels ---------------------------------------------
__global__ void k_fill_out(float* __restrict__ out, int n) {
    int i = blockIdx.x * blockDim.x + threadIdx.x;
    if (i < n) ((unsigned int*)out)[i] = 0xFF800000u;   // -inf
}

// Wc[k][c] = sum_t W_out[k][t] * W_lin1[64+t][c]
__global__ void k_wc(const float* __restrict__ Wout, const float* __restrict__ W1) {
    int idx = blockIdx.x * blockDim.x + threadIdx.x;   // 2048 = 32*64
    if (idx >= 32 * 64) return;
    int k = idx >> 6, c = idx & 63;
    float s = 0.f;
    for (int t = 0; t < 64; t++) s += Wout[k * 64 + t] * W1[(64 + t) * 64 + c];
    g_Wc[idx] = s;
}

// ---------------- K1: red = relu(x@Wred+b); scatter red; store red@W1a -----
__global__ __launch_bounds__(128) void k_red(
    const float* __restrict__ x, const float* __restrict__ W,
    const float* __restrict__ b, const float* __restrict__ W1,
    const int* __restrict__ i0, const int* __restrict__ i1,
    const int* __restrict__ i2, const int* __restrict__ i3)
{
    __shared__ float4 sW [64 * 16];   // 16 KB  W_red
    __shared__ float4 sW1[64 * 16];   // 16 KB  W_lin1 rows 0..63
    int tid = threadIdx.x;
    for (int i = tid; i < 64 * 16; i += 128) sW[i]  = ((const float4*)W)[i];
    for (int i = tid; i < 64 * 16; i += 128) sW1[i] = ((const float4*)W1)[i];
    __syncthreads();

    int v = blockIdx.x * 128 + tid;
    if (v >= NVOX) return;
    const float4* xr = (const float4*)(x + (size_t)v * 64);

    float acc[64];
#pragma unroll
    for (int c = 0; c < 64; c++) acc[c] = 0.f;

#pragma unroll
    for (int kq = 0; kq < 16; kq++) {
        float4 x4 = __ldg(xr + kq);
        float xv[4] = {x4.x, x4.y, x4.z, x4.w};
#pragma unroll
        for (int kk = 0; kk < 4; kk++) {
            int k = kq * 4 + kk;
#pragma unroll
            for (int c4 = 0; c4 < 16; c4++) {
                float4 w = sW[k * 16 + c4];
                acc[c4 * 4 + 0] += xv[kk] * w.x;
                acc[c4 * 4 + 1] += xv[kk] * w.y;
                acc[c4 * 4 + 2] += xv[kk] * w.z;
                acc[c4 * 4 + 3] += xv[kk] * w.w;
            }
        }
    }
    float red[64];
#pragma unroll
    for (int c = 0; c < 64; c++) red[c] = fmaxf(acc[c] + __ldg(b + c), 0.f);

    // scatter red into 4 per-scale segment sums
    const int* invs[4] = {i0, i1, i2, i3};
#pragma unroll
    for (int j = 0; j < 4; j++) {
        int s = __ldg(invs[j] + v);
        float* dst = g_ssum + ((size_t)j * NVOX + s) * 64;
#pragma unroll
        for (int q = 0; q < 16; q++)
            red4(dst + q * 4, red[4 * q], red[4 * q + 1], red[4 * q + 2], red[4 * q + 3]);
        atomicAdd(g_cnt + (size_t)j * NVOX + s, 1.0f);
    }

    // rW1 = red @ W1[0:64]  (two 32-col halves to bound register pressure)
    float4* rr = (float4*)(g_rW1 + (size_t)v * 64);
#pragma unroll
    for (int half = 0; half < 2; half++) {
        float a32[32];
#pragma unroll
        for (int c = 0; c < 32; c++) a32[c] = 0.f;
#pragma unroll
        for (int k = 0; k < 64; k++) {
            float xv = red[k];
#pragma unroll
            for (int c4 = 0; c4 < 8; c4++) {
                float4 w = sW1[k * 16 + half * 8 + c4];
                a32[c4 * 4 + 0] += xv * w.x;
                a32[c4 * 4 + 1] += xv * w.y;
                a32[c4 * 4 + 2] += xv * w.z;
                a32[c4 * 4 + 3] += xv * w.w;
            }
        }
#pragma unroll
        for (int q = 0; q < 8; q++)
            rr[half * 8 + q] = make_float4(a32[4 * q], a32[4 * q + 1],
                                           a32[4 * q + 2], a32[4 * q + 3]);
    }
}

// ---------------- K2: att = relu((ssum/cnt)@W_att + b); self-clean ---------
// 4 threads per segment row; thread sub computes output cols [sub*8, sub*8+8)
__global__ __launch_bounds__(256) void k_scale(
    const float* __restrict__ Watt, const float* __restrict__ batt)
{
    __shared__ float4 sA[4 * 64 * 8];   // 32 KB all 4 scales [j][k][32]
    int tid = threadIdx.x;
    for (int i = tid; i < 4 * 64 * 8; i += 256)
        sA[i] = ((const float4*)Watt)[i];
    __syncthreads();

    long long t = (long long)blockIdx.x * 256 + tid;     // 4*NVOX*4 threads
    long long row = t >> 2;
    int sub = (int)(t & 3);
    if (row >= (long long)4 * NVOX) return;
    int j = (int)(row / NVOX);
    float c = g_cnt[row];
    if (c != 0.f) {
        float invc = 1.f / c;
        float4* sp = (float4*)(g_ssum + row * 64);

        float a[8];
#pragma unroll
        for (int i = 0; i < 8; i++) a[i] = 0.f;
#pragma unroll
        for (int kq = 0; kq < 16; kq++) {
            float4 x4 = __ldg(sp + kq);
            float xv[4] = {x4.x * invc, x4.y * invc, x4.z * invc, x4.w * invc};
#pragma unroll
            for (int kk = 0; kk < 4; kk++) {
                int k = kq * 4 + kk;
                float4 w0 = sA[(j * 64 + k) * 8 + sub * 2 + 0];
                float4 w1 = sA[(j * 64 + k) * 8 + sub * 2 + 1];
                a[0] += xv[kk] * w0.x; a[1] += xv[kk] * w0.y;
                a[2] += xv[kk] * w0.z; a[3] += xv[kk] * w0.w;
                a[4] += xv[kk] * w1.x; a[5] += xv[kk] * w1.y;
                a[6] += xv[kk] * w1.z; a[7] += xv[kk] * w1.w;
            }
        }
        float4* op = (float4*)(g_att + row * 32) + sub * 2;
        float4 o0, o1;
        o0.x = fmaxf(a[0] + __ldg(batt + j * 32 + sub * 8 + 0), 0.f);
        o0.y = fmaxf(a[1] + __ldg(batt + j * 32 + sub * 8 + 1), 0.f);
        o0.z = fmaxf(a[2] + __ldg(batt + j * 32 + sub * 8 + 2), 0.f);
        o0.w = fmaxf(a[3] + __ldg(batt + j * 32 + sub * 8 + 3), 0.f);
        o1.x = fmaxf(a[4] + __ldg(batt + j * 32 + sub * 8 + 4), 0.f);
        o1.y = fmaxf(a[5] + __ldg(batt + j * 32 + sub * 8 + 5), 0.f);
        o1.z = fmaxf(a[6] + __ldg(batt + j * 32 + sub * 8 + 6), 0.f);
        o1.w = fmaxf(a[7] + __ldg(batt + j * 32 + sub * 8 + 7), 0.f);
        op[0] = o0; op[1] = o1;

        // self-clean ssum quarter (4 float4 each thread)
        float4 z = make_float4(0.f, 0.f, 0.f, 0.f);
#pragma unroll
        for (int q = 0; q < 4; q++) sp[sub * 4 + q] = z;
    }
    __syncwarp();                           // all 4 readers of cnt done
    if (c != 0.f && sub == 0) g_cnt[row] = 0.f;
}

// ---------------- K3: fusion + attention + MLP per voxel -> proj -----------
__global__ __launch_bounds__(256, 2) void k_fuse(
    const float* __restrict__ Wfc,  const float* __restrict__ Wfcs,
    const float* __restrict__ bfcs, const float* __restrict__ W2,
    const float* __restrict__ b2,
    const int* __restrict__ i0, const int* __restrict__ i1,
    const int* __restrict__ i2, const int* __restrict__ i3)
{
    __shared__ float4 sWfcs[4 * 32 * 8];   // 16 KB
    __shared__ float4 sWc  [32 * 16];      // 8 KB
    __shared__ float4 sW2  [64 * 16];      // 16 KB
    __shared__ float4 sWfc [32 * 8];       // 4 KB
    __shared__ float  sbfcs[4 * 32];
    __shared__ float  sb2  [64];

    int tid = threadIdx.x;
    for (int i = tid; i < 1024; i += 256) sWfcs[i] = ((const float4*)Wfcs)[i];
    for (int i = tid; i < 512;  i += 256) sWc[i]   = ((const float4*)g_Wc)[i];
    for (int i = tid; i < 1024; i += 256) sW2[i]   = ((const float4*)W2)[i];
    for (int i = tid; i < 256;  i += 256) sWfc[i]  = ((const float4*)Wfc)[i];
    if (tid < 128) sbfcs[tid] = bfcs[tid];
    if (tid < 64)  sb2[tid]   = b2[tid];
    __syncthreads();

    int v = blockIdx.x * 256 + tid;
    if (v >= NVOX) return;
    int sg[4] = {__ldg(i0 + v), __ldg(i1 + v), __ldg(i2 + v), __ldg(i3 + v)};

    // feat_S = sum_j s_j
    float fS[32];
#pragma unroll
    for (int i = 0; i < 32; i++) fS[i] = 0.f;
#pragma unroll
    for (int j = 0; j < 4; j++) {
        const float4* sp = (const float4*)(g_att + ((size_t)j * NVOX + sg[j]) * 32);
#pragma unroll
        for (int q = 0; q < 8; q++) {
            float4 s4 = __ldg(sp + q);
            fS[4 * q + 0] += s4.x; fS[4 * q + 1] += s4.y;
            fS[4 * q + 2] += s4.z; fS[4 * q + 3] += s4.w;
        }
    }

    // feat_Z = relu(feat_S @ W_fc)
    float fZ[32];
#pragma unroll
    for (int i = 0; i < 32; i++) fZ[i] = 0.f;
#pragma unroll
    for (int k = 0; k < 32; k++) {
        float xv = fS[k];
#pragma unroll
        for (int c4 = 0; c4 < 8; c4++) {
            float4 w = sWfc[k * 8 + c4];
            fZ[c4 * 4 + 0] += xv * w.x; fZ[c4 * 4 + 1] += xv * w.y;
            fZ[c4 * 4 + 2] += xv * w.z; fZ[c4 * 4 + 3] += xv * w.w;
        }
    }
#pragma unroll
    for (int i = 0; i < 32; i++) fZ[i] = fmaxf(fZ[i], 0.f);

    // m = sum_j s_j * sigmoid(fZ @ W_fcs[j] + b_fcs[j])   (re-gather, L1-warm)
    float m[32];
#pragma unroll
    for (int i = 0; i < 32; i++) m[i] = 0.f;
#pragma unroll
    for (int j = 0; j < 4; j++) {
        const float4* sp = (const float4*)(g_att + ((size_t)j * NVOX + sg[j]) * 32);
#pragma unroll
        for (int c4 = 0; c4 < 8; c4++) {
            float a0 = sbfcs[j * 32 + 4 * c4 + 0];
            float a1 = sbfcs[j * 32 + 4 * c4 + 1];
            float a2 = sbfcs[j * 32 + 4 * c4 + 2];
            float a3 = sbfcs[j * 32 + 4 * c4 + 3];
#pragma unroll
            for (int k = 0; k < 32; k++) {
                float4 w = sWfcs[(j * 32 + k) * 8 + c4];
                a0 += fZ[k] * w.x; a1 += fZ[k] * w.y;
                a2 += fZ[k] * w.z; a3 += fZ[k] * w.w;
            }
            float4 s4 = __ldg(sp + c4);
            m[4 * c4 + 0] += s4.x * sigm(a0);
            m[4 * c4 + 1] += s4.y * sigm(a1);
            m[4 * c4 + 2] += s4.z * sigm(a2);
            m[4 * c4 + 3] += s4.w * sigm(a3);
        }
    }

    // h = relu(rW1 + m @ Wc)
    float h[64];
    const float4* rp = (const float4*)(g_rW1 + (size_t)v * 64);
#pragma unroll
    for (int half = 0; half < 2; half++) {
        float a32[32];
#pragma unroll
        for (int q = 0; q < 8; q++) {
            float4 r4 = __ldg(rp + half * 8 + q);
            a32[4 * q + 0] = r4.x; a32[4 * q + 1] = r4.y;
            a32[4 * q + 2] = r4.z; a32[4 * q + 3] = r4.w;
        }
#pragma unroll
        for (int k = 0; k < 32; k++) {
            float xv = m[k];
#pragma unroll
            for (int c4 = 0; c4 < 8; c4++) {
                float4 w = sWc[k * 16 + half * 8 + c4];
                a32[c4 * 4 + 0] += xv * w.x; a32[c4 * 4 + 1] += xv * w.y;
                a32[c4 * 4 + 2] += xv * w.z; a32[c4 * 4 + 3] += xv * w.w;
            }
        }
#pragma unroll
        for (int c = 0; c < 32; c++) h[half * 32 + c] = fmaxf(a32[c], 0.f);
    }

    // proj = h @ W2 + b2  (two 32-col halves)
    float4* pr = (float4*)(g_proj + (size_t)v * 64);
#pragma unroll
    for (int half = 0; half < 2; half++) {
        float p32[32];
#pragma unroll
        for (int c = 0; c < 32; c++) p32[c] = sb2[half * 32 + c];
#pragma unroll
        for (int k = 0; k < 64; k++) {
            float xv = h[k];
#pragma unroll
            for (int c4 = 0; c4 < 8; c4++) {
                float4 w = sW2[k * 16 + half * 8 + c4];
                p32[c4 * 4 + 0] += xv * w.x; p32[c4 * 4 + 1] += xv * w.y;
                p32[c4 * 4 + 2] += xv * w.z; p32[c4 * 4 + 3] += xv * w.w;
            }
        }
#pragma unroll
        for (int q = 0; q < 8; q++)
            pr[half * 8 + q] = make_float4(p32[4 * q], p32[4 * q + 1],
                                           p32[4 * q + 2], p32[4 * q + 3]);
    }
}

// ---------------- K4a: point -> voxel out-row map (idempotent) --------------
__global__ __launch_bounds__(256) void k_map(
    const int* __restrict__ invp, const int* __restrict__ invo)
{
    int p = blockIdx.x * 256 + threadIdx.x;
    if (p >= NPTS) return;
    g_vout[__ldg(invp + p)] = __ldg(invo + p) + 1;
}

// ---------------- K4b: per present voxel, segment-max proj into out --------
__global__ __launch_bounds__(256) void k_pmax(float* __restrict__ out)
{
    int t = blockIdx.x * 256 + threadIdx.x;
    int v = t >> 4, q = t & 15;
    if (v >= NVOX) return;
    int o = g_vout[v];
    if (o == 0) return;                   // voxel not referenced by any point
    o--;
    float4 val = __ldg((const float4*)(g_proj + (size_t)v * 64) + q);
    float* ob = out + (size_t)o * 64 + q * 4;
    amaxf(ob + 0, val.x); amaxf(ob + 1, val.y);
    amaxf(ob + 2, val.z); amaxf(ob + 3, val.w);
}

// ---------------- launch ----------------------------------------------------
// Inputs identified by ELEMENT COUNT + first-appearance order (dict order):
//   400000 x4 -> inv0..inv3 ; 800000 x2 -> inv_pts, inv_out ; 25600000 -> x
//   4096 x3 -> W_red, W_fcs, W_lin2 ; 8192 x2 -> W_att, W_lin1
//   64 x2 -> b_red, b_lin2 ; 128 x2 -> b_att, b_fcs ; 1024 -> W_fc ; 2048 -> W_out
extern "C" void kernel_launch(void* const* d_in, const int* in_sizes, int n_in,
                              void* d_out, int out_size)
{
    const float *x = 0, *Wred = 0, *bred = 0, *Watt = 0, *batt = 0;
    const float *Wfcs = 0, *bfcs = 0, *Wfc = 0, *Wout = 0, *W1 = 0, *W2 = 0, *b2 = 0;
    const int *i0 = 0, *i1 = 0, *i2 = 0, *i3 = 0, *invp = 0, *invo = 0;

    int c400k = 0, c800k = 0, c4096 = 0, c8192 = 0, c64 = 0, c128 = 0;
    for (int i = 0; i < n_in; i++) {
        int s = in_sizes[i];
        const void* p = d_in[i];
        switch (s) {
            case 400000:
                if      (c400k == 0) i0 = (const int*)p;
                else if (c400k == 1) i1 = (const int*)p;
                else if (c400k == 2) i2 = (const int*)p;
                else                 i3 = (const int*)p;
                c400k++; break;
            case 800000:
                if (c800k == 0) invp = (const int*)p; else invo = (const int*)p;
                c800k++; break;
            case 25600000: x = (const float*)p; break;
            case 4096:
                if      (c4096 == 0) Wred = (const float*)p;
                else if (c4096 == 1) Wfcs = (const float*)p;
                else                 W2   = (const float*)p;
                c4096++; break;
            case 8192:
                if (c8192 == 0) Watt = (const float*)p; else W1 = (const float*)p;
                c8192++; break;
            case 64:
                if (c64 == 0) bred = (const float*)p; else b2 = (const float*)p;
                c64++; break;
            case 128:
                if (c128 == 0) batt = (const float*)p; else bfcs = (const float*)p;
                c128++; break;
            case 1024: Wfc  = (const float*)p; break;
            case 2048: Wout = (const float*)p; break;
            default: break;   // size-1 scalars ignored
        }
    }

    float* out = (float*)d_out;

    k_fill_out<<<(out_size + 255) / 256, 256>>>(out, out_size);

    k_wc<<<8, 256>>>(Wout, W1);

    k_map<<<(NPTS + 255) / 256, 256>>>(invp, invo);

    k_red<<<(NVOX + 127) / 128, 128>>>(x, Wred, bred, W1, i0, i1, i2, i3);

    {
        long long tot = (long long)4 * NVOX * 4;
        k_scale<<<(unsigned)((tot + 255) / 256), 256>>>(Watt, batt);
    }

    k_fuse<<<(NVOX + 255) / 256, 256>>>(Wfc, Wfcs, bfcs, W2, b2, i0, i1, i2, i3);

    k_pmax<<<((size_t)NVOX * 16 + 255) / 256, 256>>>(out);
}